// round 14
// baseline (speedup 1.0000x reference)
#include <cuda_runtime.h>
#include <cstdint>

#define BATCH   4
#define T       1024
#define HPIX    27
#define WPIX    48
#define HW      (HPIX * WPIX)   // 1296
#define NB      512
#define NK4     (NB / 4)        // 128 packed-u8 words per frame
#define LOOK    101
#define PAD     50
#define ODIM    128
#define WSTRIDE 104             // window row stride (16B aligned)
#define KSPLIT  4
#define NWIN    (BATCH * T * WSTRIDE)

#define NBLK    440             // 3 blocks/SM: resident with slack on 148 or 152 SMs
#define FPB     8               // frames per hist item
#define NHIST   512             // hist items  (4096 frames / 8)
#define NBAND   512             // band items  (4 ks x 4 batch x 32 t-blocks)
#define NFC     512             // fc items    (4096 frames / 8)
#define NITEMS  (NHIST + NBAND + NFC)

#define BK4  16
#define KQ   (NK4 / KSPLIT)     // 32 words per K-split
#define NCHU (KQ / BK4)         // 2 chunks
#define TBLK 32
#define HSW  136                // strip: u in [tb-50, tb+85]

// Scratch + sync (device globals; zero-initialized at load, reset at kernel end)
__device__ uint32_t g_histP[BATCH * NK4 * T];
__device__ float    g_invn[BATCH * T];
__device__ uint32_t g_winP[KSPLIT * NWIN];
__device__ int      g_fdone[NHIST];        // hist item done flags
__device__ int      g_bdone[BATCH * 32];   // per-t-block band completion counters (to 4)
__device__ int      g_exit;                // block exit counter (last block resets flags)

union SmemU {
    int      hist[FPB * NB];                       // 16384 B
    uint32_t strip[2][BK4][HSW];                   // 17408 B
    struct { float inv[112]; float wins[8][WSTRIDE]; } fc;
};

// bounded spin: a real deadlock fails the test instead of killing the container
__device__ __forceinline__ void wait_ge(volatile int* p, int target) {
    int tries = 0;
    while (*p < target) {
        __nanosleep(100);
        if (++tries > 4000000) break;   // ~0.4 s cap
    }
}

__global__ void __launch_bounds__(256, 3)
fused_kernel(const int* __restrict__ frames, const float* __restrict__ fc_w,
             const float* __restrict__ fc_b, float* __restrict__ out) {
    __shared__ SmemU sm;
    const int tid = threadIdx.x;

    for (int idx = blockIdx.x; idx < NITEMS; idx += NBLK) {
        if (idx < NHIST) {
            // ================= hist item: 8 frames =================
            const int h  = idx;
            const int f0 = h * FPB;
            int* sh = sm.hist;
            for (int i = tid; i < FPB * NB; i += 256) sh[i] = 0;
            __syncthreads();

            const int4* base = (const int4*)(frames + (size_t)f0 * HW * 3);
            const int NG = FPB * (HW / 4);            // 2592 quad-pixel groups
            int  g = tid;
            int4 w0, w1, w2;
            if (g < NG) { w0 = base[3*g]; w1 = base[3*g+1]; w2 = base[3*g+2]; }
            while (g < NG) {
                const int gn = g + 256;
                int4 n0, n1, n2;
                if (gn < NG) { n0 = base[3*gn]; n1 = base[3*gn+1]; n2 = base[3*gn+2]; }
                int* hh = sh + (g / (HW / 4)) * NB;
                atomicAdd(&hh[((w0.x >> 5) << 6) | ((w0.y >> 5) << 3) | (w0.z >> 5)], 1);
                atomicAdd(&hh[((w0.w >> 5) << 6) | ((w1.x >> 5) << 3) | (w1.y >> 5)], 1);
                atomicAdd(&hh[((w1.z >> 5) << 6) | ((w1.w >> 5) << 3) | (w2.x >> 5)], 1);
                atomicAdd(&hh[((w2.y >> 5) << 6) | ((w2.z >> 5) << 3) | (w2.w >> 5)], 1);
                g = gn; w0 = n0; w1 = n1; w2 = n2;
            }
            __syncthreads();

            // inverse norms: warp w handles frame w (8 warps, 8 frames)
            const int lane = tid & 31, w = tid >> 5;
            {
                float ss = 0.f;
                #pragma unroll
                for (int k = lane; k < NB; k += 32) {
                    float c = (float)sh[w * NB + k];
                    ss = fmaf(c, c, ss);
                }
                #pragma unroll
                for (int off = 16; off; off >>= 1) ss += __shfl_xor_sync(0xffffffffu, ss, off);
                if (lane == 0) g_invn[f0 + w] = rsqrtf(ss);
            }

            // pack u8x4, k-major transposed
            const int b  = f0 >> 10;
            const int t0 = f0 & (T - 1);
            for (int i = tid; i < NK4 * FPB; i += 256) {
                int f  = i & (FPB - 1);
                int k4 = i >> 3;
                int s  = f * NB + k4 * 4;
                uint32_t c0 = min(sh[s+0], 255), c1 = min(sh[s+1], 255);
                uint32_t c2 = min(sh[s+2], 255), c3 = min(sh[s+3], 255);
                g_histP[(b * NK4 + k4) * T + t0 + f] = c0 | (c1 << 8) | (c2 << 16) | (c3 << 24);
            }
            __syncthreads();
            if (tid == 0) { __threadfence(); atomicExch(&g_fdone[h], 1); }

        } else if (idx < NHIST + NBAND) {
            // ================= band item: 32t x 104l x 32K-words =================
            const int ib  = idx - NHIST;
            const int ks  = ib >> 7;
            const int rem = ib & 127;
            const int bb  = rem >> 5;
            const int tbi = rem & 31;
            const int tb  = tbi * TBLK;

            // wait for the hist items covering frames [tb-50, tb+85]
            if (tid == 0) {
                int lo = (bb * T + max(0, tb - PAD)) >> 3;
                int hi = (bb * T + min(T - 1, tb + 85)) >> 3;
                for (int f = lo; f <= hi; f++) wait_ge(&g_fdone[f], 1);
                __threadfence();
            }
            __syncthreads();

            const int  ty  = tid / 26;
            const int  tx  = tid - ty * 26;
            const bool act = (tid < 208);
            const int  j0  = ty * 4 + tx * 4;
            const int  ja  = ty * 4 + PAD;

            unsigned int acc[4][4];
            #pragma unroll
            for (int r = 0; r < 4; r++)
                #pragma unroll
                for (int c = 0; c < 4; c++) acc[r][c] = 0u;

            const uint32_t* hb = g_histP + (size_t)bb * NK4 * T + (size_t)ks * KQ * T;

            // load chunk 0
            for (int i = tid; i < BK4 * HSW; i += 256) {
                int k = i / HSW, j = i - k * HSW;
                int u = tb - PAD + j;
                uint32_t v = 0u;
                if ((unsigned)u < (unsigned)T) v = hb[(size_t)k * T + u];
                sm.strip[0][k][j] = v;
            }
            __syncthreads();

            #pragma unroll
            for (int ch = 0; ch < NCHU; ch++) {
                const int cur = ch & 1;
                if (ch + 1 < NCHU) {
                    for (int i = tid; i < BK4 * HSW; i += 256) {
                        int k = i / HSW, j = i - k * HSW;
                        int u = tb - PAD + j;
                        uint32_t v = 0u;
                        if ((unsigned)u < (unsigned)T)
                            v = hb[(size_t)((ch + 1) * BK4 + k) * T + u];
                        sm.strip[cur ^ 1][k][j] = v;
                    }
                }
                if (act) {
                    #pragma unroll
                    for (int k = 0; k < BK4; k++) {
                        uint2 a0 = *(const uint2*)&sm.strip[cur][k][ja];
                        uint2 a1 = *(const uint2*)&sm.strip[cur][k][ja + 2];
                        uint4 b0 = *(const uint4*)&sm.strip[cur][k][j0];
                        uint4 b1 = *(const uint4*)&sm.strip[cur][k][j0 + 4];
                        unsigned int ar[4] = {a0.x, a0.y, a1.x, a1.y};
                        unsigned int bw[8] = {b0.x, b0.y, b0.z, b0.w, b1.x, b1.y, b1.z, b1.w};
                        #pragma unroll
                        for (int r = 0; r < 4; r++)
                            #pragma unroll
                            for (int c = 0; c < 4; c++)
                                acc[r][c] = __dp4a(ar[r], bw[r + c], acc[r][c]);
                    }
                }
                __syncthreads();
            }

            if (act) {
                uint32_t* slab = g_winP + (size_t)ks * NWIN;
                #pragma unroll
                for (int r = 0; r < 4; r++) {
                    int t = tb + ty * 4 + r;
                    uint4 v = make_uint4(acc[r][0], acc[r][1], acc[r][2], acc[r][3]);
                    *(uint4*)&slab[(size_t)(bb * T + t) * WSTRIDE + tx * 4] = v;
                }
            }
            __syncthreads();
            if (tid == 0) { __threadfence(); atomicAdd(&g_bdone[bb * 32 + tbi], 1); }

        } else {
            // ================= fc item: 8 output rows =================
            const int ifc = idx - NHIST - NBAND;
            const int g0  = ifc * 8;
            const int t0  = g0 & (T - 1);
            const int bb  = g0 >> 10;
            const int tbi = t0 >> 5;

            const int txo = (tid & 31) * 4;
            const int r   = tid >> 5;
            float4 b4 = *(const float4*)(fc_b + txo);    // independent preamble

            if (tid == 0) {
                wait_ge(&g_bdone[bb * 32 + tbi], KSPLIT);
                __threadfence();
            }
            __syncthreads();

            for (int i = tid; i < 108; i += 256) {
                int u = t0 - PAD + i;
                sm.fc.inv[i] = ((unsigned)u < (unsigned)T) ? g_invn[bb * T + u] : 0.f;
            }
            __syncthreads();

            for (int i = tid; i < 8 * (WSTRIDE / 4); i += 256) {
                int rr = i / (WSTRIDE / 4), q = i - rr * (WSTRIDE / 4);
                int l = q * 4;
                size_t off = (size_t)(g0 + rr) * WSTRIDE + l;
                uint4 s0 = *(const uint4*)&g_winP[0 * NWIN + off];
                uint4 s1 = *(const uint4*)&g_winP[1 * NWIN + off];
                uint4 s2 = *(const uint4*)&g_winP[2 * NWIN + off];
                uint4 s3 = *(const uint4*)&g_winP[3 * NWIN + off];
                uint4 wi = make_uint4(s0.x + s1.x + s2.x + s3.x,
                                      s0.y + s1.y + s2.y + s3.y,
                                      s0.z + s1.z + s2.z + s3.z,
                                      s0.w + s1.w + s2.w + s3.w);
                float ivt = sm.fc.inv[rr + PAD];
                sm.fc.wins[rr][l+0] = (l+0 < LOOK) ? (float)wi.x * ivt * sm.fc.inv[rr+l+0] : 0.f;
                sm.fc.wins[rr][l+1] = (l+1 < LOOK) ? (float)wi.y * ivt * sm.fc.inv[rr+l+1] : 0.f;
                sm.fc.wins[rr][l+2] = (l+2 < LOOK) ? (float)wi.z * ivt * sm.fc.inv[rr+l+2] : 0.f;
                sm.fc.wins[rr][l+3] = (l+3 < LOOK) ? (float)wi.w * ivt * sm.fc.inv[rr+l+3] : 0.f;
            }
            __syncthreads();

            float a0o = b4.x, a1o = b4.y, a2o = b4.z, a3o = b4.w;
            for (int l = 0; l < LOOK; l++) {
                float4 wv = *(const float4*)(fc_w + l * ODIM + txo);
                float a = sm.fc.wins[r][l];
                a0o = fmaf(a, wv.x, a0o);
                a1o = fmaf(a, wv.y, a1o);
                a2o = fmaf(a, wv.z, a2o);
                a3o = fmaf(a, wv.w, a3o);
            }
            float4 o4;
            o4.x = fmaxf(a0o, 0.f);
            o4.y = fmaxf(a1o, 0.f);
            o4.z = fmaxf(a2o, 0.f);
            o4.w = fmaxf(a3o, 0.f);
            *(float4*)(out + (size_t)(g0 + r) * ODIM + txo) = o4;
        }
        __syncthreads();   // smem union reuse barrier between items
    }

    // last block to exit resets all sync state for the next graph replay
    if (tid == 0) {
        int old = atomicAdd(&g_exit, 1);
        if (old == NBLK - 1) {
            for (int i = 0; i < NHIST; i++)      g_fdone[i] = 0;
            for (int i = 0; i < BATCH * 32; i++) g_bdone[i] = 0;
            __threadfence();
            g_exit = 0;
        }
    }
}

// ---------------------------------------------------------------------------
extern "C" void kernel_launch(void* const* d_in, const int* in_sizes, int n_in,
                              void* d_out, int out_size) {
    const int*   frames = (const int*)d_in[0];
    const float* fc_w   = (const float*)d_in[1];
    const float* fc_b   = (const float*)d_in[2];
    float*       out    = (float*)d_out;

    fused_kernel<<<NBLK, 256>>>(frames, fc_w, fc_b, out);
}

// round 15
// speedup vs baseline: 1.1566x; 1.1566x over previous
#include <cuda_runtime.h>
#include <cstdint>

#define BATCH   4
#define T       1024
#define HPIX    27
#define WPIX    48
#define HW      (HPIX * WPIX)   // 1296
#define NB      512
#define NK4     (NB / 4)        // 128 packed-u8 words per frame
#define LOOK    101
#define PAD     50
#define ODIM    128
#define WSTRIDE 104             // window row stride (16B aligned)
#define KSPLIT  4
#define NWIN    (BATCH * T * WSTRIDE)
#define NSLICE  2               // batch slices for the pipeline
#define BPS     (BATCH / NSLICE)

// Scratch (device globals; no allocation in kernel_launch per harness rules)
__device__ uint32_t g_histP[BATCH * NK4 * T];     // packed u8 counts, [b][k4][t]
__device__ float    g_invn[BATCH * T];            // 1/||hist||
__device__ uint32_t g_winP[KSPLIT * NWIN];        // per-K-split integer partial windows

// ---------------------------------------------------------------------------
// Kernel 1: per-frame 512-bin color histogram -> packed u8 counts (transposed)
// + inverse L2 norm. Parameterized by global frame offset (batch slice).
// ---------------------------------------------------------------------------
#define FPB 4
#define GPF (HW / 4)            // 324 quad-pixel groups per frame
#define NGRP (FPB * GPF)        // 1296
__global__ void __launch_bounds__(256) hist_kernel(const int* __restrict__ frames,
                                                   int fbase) {
    __shared__ int sh[FPB * NB];                      // 8 KB
    const int tid = threadIdx.x;
    const int f0  = fbase + blockIdx.x * FPB;         // global frame base

    #pragma unroll
    for (int i = tid; i < FPB * NB; i += 256) sh[i] = 0;
    __syncthreads();

    const int4* base = (const int4*)(frames + (size_t)f0 * HW * 3);
    int  g = tid;
    int4 w0, w1, w2;
    if (g < NGRP) {
        w0 = base[3 * g + 0];
        w1 = base[3 * g + 1];
        w2 = base[3 * g + 2];
    }
    while (g < NGRP) {
        const int gn = g + 256;
        int4 n0, n1, n2;
        if (gn < NGRP) {                // prefetch next iteration
            n0 = base[3 * gn + 0];
            n1 = base[3 * gn + 1];
            n2 = base[3 * gn + 2];
        }
        int* h = sh + (g / GPF) * NB;
        atomicAdd(&h[((w0.x >> 5) << 6) | ((w0.y >> 5) << 3) | (w0.z >> 5)], 1);
        atomicAdd(&h[((w0.w >> 5) << 6) | ((w1.x >> 5) << 3) | (w1.y >> 5)], 1);
        atomicAdd(&h[((w1.z >> 5) << 6) | ((w1.w >> 5) << 3) | (w2.x >> 5)], 1);
        atomicAdd(&h[((w2.y >> 5) << 6) | ((w2.z >> 5) << 3) | (w2.w >> 5)], 1);
        g = gn; w0 = n0; w1 = n1; w2 = n2;
    }
    __syncthreads();

    // inverse norms: warp w handles frame w
    const int lane = tid & 31, w = tid >> 5;
    if (w < FPB) {
        float ss = 0.f;
        #pragma unroll
        for (int k = lane; k < NB; k += 32) {
            float c = (float)sh[w * NB + k];
            ss = fmaf(c, c, ss);
        }
        #pragma unroll
        for (int off = 16; off; off >>= 1) ss += __shfl_xor_sync(0xffffffffu, ss, off);
        if (lane == 0) g_invn[f0 + w] = rsqrtf(ss);   // ss >= 1 always
    }

    // pack 4 consecutive bins into u8x4, write k-major (transposed)
    const int b  = f0 >> 10;
    const int t0 = f0 & (T - 1);
    #pragma unroll
    for (int i = tid; i < NK4 * FPB; i += 256) {
        int f  = i & (FPB - 1);
        int k4 = i >> 2;
        int s  = f * NB + k4 * 4;
        uint32_t c0 = min(sh[s + 0], 255), c1 = min(sh[s + 1], 255);
        uint32_t c2 = min(sh[s + 2], 255), c3 = min(sh[s + 3], 255);
        g_histP[(b * NK4 + k4) * T + t0 + f] = c0 | (c1 << 8) | (c2 << 16) | (c3 << 24);
    }
}

// ---------------------------------------------------------------------------
// Kernel 2: banded correlation, W[t][l] = dot(h[t], h[t+l-50]) in (t,l)
// layout; plain uint4 stores to per-K-split slabs. Parameterized by batch base.
// ---------------------------------------------------------------------------
#define BK4  16
#define KQ   (NK4 / KSPLIT)     // 32 words per K-split
#define NCH  (KQ / BK4)         // 2 chunks
#define TBLK 32
#define HSW  136                // strip: u in [tb-50, tb+85]

__global__ void __launch_bounds__(256) band_kernel(int bbase) {
    const int bb = bbase + blockIdx.y;
    const int ks = blockIdx.z;
    const int tb = blockIdx.x * TBLK;

    __shared__ uint32_t Hs[2][BK4][HSW];   // 17.4 KB double-buffered strip

    const int tid = threadIdx.x;
    const int  ty  = tid / 26;
    const int  tx  = tid - ty * 26;
    const bool act = (tid < 208);
    const int  j0  = ty * 4 + tx * 4;      // B window base (16B aligned)
    const int  ja  = ty * 4 + PAD;         // A base within strip (8B aligned)

    unsigned int acc[4][4];
    #pragma unroll
    for (int r = 0; r < 4; r++)
        #pragma unroll
        for (int c = 0; c < 4; c++) acc[r][c] = 0u;

    const uint32_t* hb = g_histP + (size_t)bb * NK4 * T + (size_t)ks * KQ * T;

    auto load_chunk = [&](int ch, int buf) {
        #pragma unroll
        for (int i = tid; i < BK4 * HSW; i += 256) {
            int k = i / HSW, j = i - k * HSW;
            int u = tb - PAD + j;
            uint32_t v = 0u;
            if ((unsigned)u < (unsigned)T) v = hb[(size_t)(ch * BK4 + k) * T + u];
            Hs[buf][k][j] = v;
        }
    };

    load_chunk(0, 0);
    __syncthreads();

    #pragma unroll
    for (int ch = 0; ch < NCH; ch++) {
        const int cur = ch & 1;
        if (ch + 1 < NCH) load_chunk(ch + 1, cur ^ 1);
        if (act) {
            #pragma unroll
            for (int k = 0; k < BK4; k++) {
                uint2 a0 = *(const uint2*)&Hs[cur][k][ja];
                uint2 a1 = *(const uint2*)&Hs[cur][k][ja + 2];
                uint4 b0 = *(const uint4*)&Hs[cur][k][j0];
                uint4 b1 = *(const uint4*)&Hs[cur][k][j0 + 4];
                unsigned int ar[4] = {a0.x, a0.y, a1.x, a1.y};
                unsigned int bw[8] = {b0.x, b0.y, b0.z, b0.w, b1.x, b1.y, b1.z, b1.w};
                #pragma unroll
                for (int r = 0; r < 4; r++)
                    #pragma unroll
                    for (int c = 0; c < 4; c++)
                        acc[r][c] = __dp4a(ar[r], bw[r + c], acc[r][c]);
            }
        }
        __syncthreads();
    }

    if (act) {
        uint32_t* slab = g_winP + (size_t)ks * NWIN;
        #pragma unroll
        for (int r = 0; r < 4; r++) {
            int t = tb + ty * 4 + r;
            uint4 v = make_uint4(acc[r][0], acc[r][1], acc[r][2], acc[r][3]);
            *(uint4*)&slab[(size_t)(bb * T + t) * WSTRIDE + tx * 4] = v;
        }
    }
}

// ---------------------------------------------------------------------------
// Kernel 3: out = relu(win @ fc_w + fc_b), win = (sum of 4 slabs) *
// invn[t] * invn[u], boundary-zeroed. Parameterized by batch base.
// ---------------------------------------------------------------------------
__global__ void __launch_bounds__(256) fc_kernel(const float* __restrict__ fc_w,
                                                 const float* __restrict__ fc_b,
                                                 float* __restrict__ out,
                                                 int bbase) {
    const int tid = threadIdx.x;
    const int g0  = bbase * T + blockIdx.x * 8;   // global frame base
    const int t0  = g0 & (T - 1);
    const int bb  = g0 >> 10;

    __shared__ float sInv[112];
    __shared__ float wins[8][WSTRIDE];

    for (int i = tid; i < 108; i += 256) {
        int u = t0 - PAD + i;
        sInv[i] = ((unsigned)u < (unsigned)T) ? g_invn[bb * T + u] : 0.f;
    }
    __syncthreads();

    for (int i = tid; i < 8 * (WSTRIDE / 4); i += 256) {
        int rr = i / (WSTRIDE / 4), q = i - rr * (WSTRIDE / 4);
        int l = q * 4;
        size_t off = (size_t)(g0 + rr) * WSTRIDE + l;
        uint4 s0 = *(const uint4*)&g_winP[0 * NWIN + off];
        uint4 s1 = *(const uint4*)&g_winP[1 * NWIN + off];
        uint4 s2 = *(const uint4*)&g_winP[2 * NWIN + off];
        uint4 s3 = *(const uint4*)&g_winP[3 * NWIN + off];
        uint4 wi = make_uint4(s0.x + s1.x + s2.x + s3.x,
                              s0.y + s1.y + s2.y + s3.y,
                              s0.z + s1.z + s2.z + s3.z,
                              s0.w + s1.w + s2.w + s3.w);
        float ivt = sInv[rr + PAD];
        wins[rr][l + 0] = (l + 0 < LOOK) ? (float)wi.x * ivt * sInv[rr + l + 0] : 0.f;
        wins[rr][l + 1] = (l + 1 < LOOK) ? (float)wi.y * ivt * sInv[rr + l + 1] : 0.f;
        wins[rr][l + 2] = (l + 2 < LOOK) ? (float)wi.z * ivt * sInv[rr + l + 2] : 0.f;
        wins[rr][l + 3] = (l + 3 < LOOK) ? (float)wi.w * ivt * sInv[rr + l + 3] : 0.f;
    }
    __syncthreads();

    const int tx = (tid & 31) * 4;
    const int r  = tid >> 5;

    float4 b4 = *(const float4*)(fc_b + tx);
    float a0o = b4.x, a1o = b4.y, a2o = b4.z, a3o = b4.w;

    for (int l = 0; l < LOOK; l++) {
        float4 wv = *(const float4*)(fc_w + l * ODIM + tx);
        float a = wins[r][l];
        a0o = fmaf(a, wv.x, a0o);
        a1o = fmaf(a, wv.y, a1o);
        a2o = fmaf(a, wv.z, a2o);
        a3o = fmaf(a, wv.w, a3o);
    }

    float4 o4;
    o4.x = fmaxf(a0o, 0.f);
    o4.y = fmaxf(a1o, 0.f);
    o4.z = fmaxf(a2o, 0.f);
    o4.w = fmaxf(a3o, 0.f);
    *(float4*)(out + (size_t)(g0 + r) * ODIM + tx) = o4;
}

// ---------------------------------------------------------------------------
// Pipelined launch: main stream runs hist slices back-to-back; a side stream
// (forked/joined with events — standard capturable pattern) runs band+fc for
// slice s concurrently with hist of slice s+1.
// ---------------------------------------------------------------------------
extern "C" void kernel_launch(void* const* d_in, const int* in_sizes, int n_in,
                              void* d_out, int out_size) {
    const int*   frames = (const int*)d_in[0];
    const float* fc_w   = (const float*)d_in[1];
    const float* fc_b   = (const float*)d_in[2];
    float*       out    = (float*)d_out;

    static bool         s_init = false;
    static cudaStream_t s_side;
    static cudaEvent_t  s_fork[NSLICE], s_join[NSLICE];
    if (!s_init) {
        cudaStreamCreateWithFlags(&s_side, cudaStreamNonBlocking);
        for (int s = 0; s < NSLICE; s++) {
            cudaEventCreateWithFlags(&s_fork[s], cudaEventDisableTiming);
            cudaEventCreateWithFlags(&s_join[s], cudaEventDisableTiming);
        }
        s_init = true;
    }

    for (int s = 0; s < NSLICE; s++) {
        const int fbase = s * BPS * T;      // first frame of this slice
        const int bbase = s * BPS;          // first batch of this slice

        hist_kernel<<<(BPS * T) / FPB, 256, 0, 0>>>(frames, fbase);   // 512 blocks
        cudaEventRecord(s_fork[s], 0);
        cudaStreamWaitEvent(s_side, s_fork[s], 0);

        band_kernel<<<dim3(T / TBLK, BPS, KSPLIT), 256, 0, s_side>>>(bbase); // 256 blocks
        fc_kernel<<<(BPS * T) / 8, 256, 0, s_side>>>(fc_w, fc_b, out, bbase); // 256 blocks
        cudaEventRecord(s_join[s], s_side);
    }
    for (int s = 0; s < NSLICE; s++)
        cudaStreamWaitEvent(0, s_join[s], 0);
}

// round 16
// speedup vs baseline: 1.3779x; 1.1913x over previous
#include <cuda_runtime.h>
#include <cstdint>

#define BATCH   4
#define T       1024
#define HPIX    27
#define WPIX    48
#define HW      (HPIX * WPIX)   // 1296
#define NB      512
#define NK4     (NB / 4)        // 128 packed-u8 words per frame
#define LOOK    101
#define PAD     50
#define ODIM    128
#define WSTRIDE 104             // window row stride (16B aligned)
#define KSPLIT  4
#define NWIN    (BATCH * T * WSTRIDE)

// Scratch (device globals; no allocation in kernel_launch per harness rules)
__device__ uint32_t g_histP[BATCH * NK4 * T];     // packed u8 counts, [b][k4][t]
__device__ float    g_invn[BATCH * T];            // 1/||hist||
__device__ uint32_t g_winP[KSPLIT * NWIN];        // per-K-split integer partial windows

// ---------------------------------------------------------------------------
// Kernel 1: per-frame 512-bin color histogram -> packed u8 counts (transposed)
// + inverse L2 norm. (R4/R11 form.)
// ---------------------------------------------------------------------------
#define FPB 4
#define GPF (HW / 4)            // 324 quad-pixel groups per frame
#define NGRP (FPB * GPF)        // 1296
__global__ void __launch_bounds__(256) hist_kernel(const int* __restrict__ frames) {
    __shared__ int sh[FPB * NB];                      // 8 KB
    const int tid = threadIdx.x;
    const int f0  = blockIdx.x * FPB;                 // global frame base

    #pragma unroll
    for (int i = tid; i < FPB * NB; i += 256) sh[i] = 0;
    __syncthreads();

    const int4* base = (const int4*)(frames + (size_t)f0 * HW * 3);
    int  g = tid;
    int4 w0, w1, w2;
    if (g < NGRP) {
        w0 = base[3 * g + 0];
        w1 = base[3 * g + 1];
        w2 = base[3 * g + 2];
    }
    while (g < NGRP) {
        const int gn = g + 256;
        int4 n0, n1, n2;
        if (gn < NGRP) {                // prefetch next iteration
            n0 = base[3 * gn + 0];
            n1 = base[3 * gn + 1];
            n2 = base[3 * gn + 2];
        }
        int* h = sh + (g / GPF) * NB;
        atomicAdd(&h[((w0.x >> 5) << 6) | ((w0.y >> 5) << 3) | (w0.z >> 5)], 1);
        atomicAdd(&h[((w0.w >> 5) << 6) | ((w1.x >> 5) << 3) | (w1.y >> 5)], 1);
        atomicAdd(&h[((w1.z >> 5) << 6) | ((w1.w >> 5) << 3) | (w2.x >> 5)], 1);
        atomicAdd(&h[((w2.y >> 5) << 6) | ((w2.z >> 5) << 3) | (w2.w >> 5)], 1);
        g = gn; w0 = n0; w1 = n1; w2 = n2;
    }
    __syncthreads();

    // inverse norms: warp w handles frame w
    const int lane = tid & 31, w = tid >> 5;
    if (w < FPB) {
        float ss = 0.f;
        #pragma unroll
        for (int k = lane; k < NB; k += 32) {
            float c = (float)sh[w * NB + k];
            ss = fmaf(c, c, ss);
        }
        #pragma unroll
        for (int off = 16; off; off >>= 1) ss += __shfl_xor_sync(0xffffffffu, ss, off);
        if (lane == 0) g_invn[f0 + w] = rsqrtf(ss);   // ss >= 1 always
    }

    // pack 4 consecutive bins into u8x4, write k-major (transposed)
    const int b  = f0 >> 10;
    const int t0 = f0 & (T - 1);
    #pragma unroll
    for (int i = tid; i < NK4 * FPB; i += 256) {
        int f  = i & (FPB - 1);
        int k4 = i >> 2;
        int s  = f * NB + k4 * 4;
        uint32_t c0 = min(sh[s + 0], 255), c1 = min(sh[s + 1], 255);
        uint32_t c2 = min(sh[s + 2], 255), c3 = min(sh[s + 3], 255);
        g_histP[(b * NK4 + k4) * T + t0 + f] = c0 | (c1 << 8) | (c2 << 16) | (c3 << 24);
    }
}

// ---------------------------------------------------------------------------
// Kernel 2: banded correlation, W[t][l] = dot(h[t], h[t+l-50]) in (t,l)
// layout; plain uint4 stores to per-K-split slabs. (R11 form, unchanged.)
// Grid: 32 t-blocks x 4 batches x 4 K-splits = 512 blocks (~3.4/SM).
// ---------------------------------------------------------------------------
#define BK4  16
#define KQ   (NK4 / KSPLIT)     // 32 words per K-split
#define NCH  (KQ / BK4)         // 2 chunks
#define TBLK 32
#define HSW  136                // strip: u in [tb-50, tb+85]

__global__ void __launch_bounds__(256) band_kernel() {
    const int bb = blockIdx.y;
    const int ks = blockIdx.z;
    const int tb = blockIdx.x * TBLK;

    __shared__ uint32_t Hs[2][BK4][HSW];   // 17.4 KB double-buffered strip

    const int tid = threadIdx.x;
    const int  ty  = tid / 26;
    const int  tx  = tid - ty * 26;
    const bool act = (tid < 208);
    const int  j0  = ty * 4 + tx * 4;      // B window base (16B aligned)
    const int  ja  = ty * 4 + PAD;         // A base within strip (8B aligned)

    unsigned int acc[4][4];
    #pragma unroll
    for (int r = 0; r < 4; r++)
        #pragma unroll
        for (int c = 0; c < 4; c++) acc[r][c] = 0u;

    const uint32_t* hb = g_histP + (size_t)bb * NK4 * T + (size_t)ks * KQ * T;

    auto load_chunk = [&](int ch, int buf) {
        #pragma unroll
        for (int i = tid; i < BK4 * HSW; i += 256) {
            int k = i / HSW, j = i - k * HSW;
            int u = tb - PAD + j;
            uint32_t v = 0u;
            if ((unsigned)u < (unsigned)T) v = hb[(size_t)(ch * BK4 + k) * T + u];
            Hs[buf][k][j] = v;
        }
    };

    load_chunk(0, 0);
    __syncthreads();

    #pragma unroll
    for (int ch = 0; ch < NCH; ch++) {
        const int cur = ch & 1;
        if (ch + 1 < NCH) load_chunk(ch + 1, cur ^ 1);
        if (act) {
            #pragma unroll
            for (int k = 0; k < BK4; k++) {
                uint2 a0 = *(const uint2*)&Hs[cur][k][ja];
                uint2 a1 = *(const uint2*)&Hs[cur][k][ja + 2];
                uint4 b0 = *(const uint4*)&Hs[cur][k][j0];
                uint4 b1 = *(const uint4*)&Hs[cur][k][j0 + 4];
                unsigned int ar[4] = {a0.x, a0.y, a1.x, a1.y};
                unsigned int bw[8] = {b0.x, b0.y, b0.z, b0.w, b1.x, b1.y, b1.z, b1.w};
                #pragma unroll
                for (int r = 0; r < 4; r++)
                    #pragma unroll
                    for (int c = 0; c < 4; c++)
                        acc[r][c] = __dp4a(ar[r], bw[r + c], acc[r][c]);
            }
        }
        __syncthreads();
    }

    if (act) {
        uint32_t* slab = g_winP + (size_t)ks * NWIN;
        #pragma unroll
        for (int r = 0; r < 4; r++) {
            int t = tb + ty * 4 + r;
            uint4 v = make_uint4(acc[r][0], acc[r][1], acc[r][2], acc[r][3]);
            *(uint4*)&slab[(size_t)(bb * T + t) * WSTRIDE + tx * 4] = v;
        }
    }
}

// ---------------------------------------------------------------------------
// Kernel 3: out = relu(win @ fc_w + fc_b), win = (sum of 4 slabs) *
// invn[t] * invn[u], boundary-zeroed.
// R16: 16 rows per block (256 blocks) — halves per-row amortization of
// sInv staging, window staging, syncs, and launch overhead vs the 8-row
// version. 256 threads = 32 ch-groups x 8 row-pairs; 2 rows x 4 ch each.
// ---------------------------------------------------------------------------
#define FROWS 16
__global__ void __launch_bounds__(256) fc_kernel(const float* __restrict__ fc_w,
                                                 const float* __restrict__ fc_b,
                                                 float* __restrict__ out) {
    const int tid = threadIdx.x;
    const int g0  = blockIdx.x * FROWS;     // global frame base
    const int t0  = g0 & (T - 1);           // within-batch index
    const int bb  = g0 >> 10;

    __shared__ float sInv[120];             // invn[t0-50 .. t0+65], 0 outside batch
    __shared__ float wins[FROWS][WSTRIDE];

    for (int i = tid; i < FROWS + 104; i += 256) {   // 120 values
        int u = t0 - PAD + i;
        sInv[i] = ((unsigned)u < (unsigned)T) ? g_invn[bb * T + u] : 0.f;
    }
    __syncthreads();

    // stage window: sum 4 K-split slabs, normalize, boundary-zero
    for (int i = tid; i < FROWS * (WSTRIDE / 4); i += 256) {
        int rr = i / (WSTRIDE / 4), q = i - rr * (WSTRIDE / 4);
        int l = q * 4;
        size_t off = (size_t)(g0 + rr) * WSTRIDE + l;
        uint4 s0 = *(const uint4*)&g_winP[0 * NWIN + off];
        uint4 s1 = *(const uint4*)&g_winP[1 * NWIN + off];
        uint4 s2 = *(const uint4*)&g_winP[2 * NWIN + off];
        uint4 s3 = *(const uint4*)&g_winP[3 * NWIN + off];
        uint4 wi = make_uint4(s0.x + s1.x + s2.x + s3.x,
                              s0.y + s1.y + s2.y + s3.y,
                              s0.z + s1.z + s2.z + s3.z,
                              s0.w + s1.w + s2.w + s3.w);
        float ivt = sInv[rr + PAD];
        wins[rr][l + 0] = (l + 0 < LOOK) ? (float)wi.x * ivt * sInv[rr + l + 0] : 0.f;
        wins[rr][l + 1] = (l + 1 < LOOK) ? (float)wi.y * ivt * sInv[rr + l + 1] : 0.f;
        wins[rr][l + 2] = (l + 2 < LOOK) ? (float)wi.z * ivt * sInv[rr + l + 2] : 0.f;
        wins[rr][l + 3] = (l + 3 < LOOK) ? (float)wi.w * ivt * sInv[rr + l + 3] : 0.f;
    }
    __syncthreads();

    const int tx = (tid & 31) * 4;          // output-channel base (0..124)
    const int r0 = (tid >> 5) * 2;          // row-pair base (0,2,..,14)

    float4 b4 = *(const float4*)(fc_b + tx);
    float a0o = b4.x, a1o = b4.y, a2o = b4.z, a3o = b4.w;
    float c0o = b4.x, c1o = b4.y, c2o = b4.z, c3o = b4.w;

    for (int l = 0; l < LOOK; l++) {
        float4 wv = *(const float4*)(fc_w + l * ODIM + tx);
        float a = wins[r0 + 0][l];
        float c = wins[r0 + 1][l];
        a0o = fmaf(a, wv.x, a0o); a1o = fmaf(a, wv.y, a1o);
        a2o = fmaf(a, wv.z, a2o); a3o = fmaf(a, wv.w, a3o);
        c0o = fmaf(c, wv.x, c0o); c1o = fmaf(c, wv.y, c1o);
        c2o = fmaf(c, wv.z, c2o); c3o = fmaf(c, wv.w, c3o);
    }

    float4 o4;
    o4.x = fmaxf(a0o, 0.f); o4.y = fmaxf(a1o, 0.f);
    o4.z = fmaxf(a2o, 0.f); o4.w = fmaxf(a3o, 0.f);
    *(float4*)(out + (size_t)(g0 + r0) * ODIM + tx) = o4;
    o4.x = fmaxf(c0o, 0.f); o4.y = fmaxf(c1o, 0.f);
    o4.z = fmaxf(c2o, 0.f); o4.w = fmaxf(c3o, 0.f);
    *(float4*)(out + (size_t)(g0 + r0 + 1) * ODIM + tx) = o4;
}

// ---------------------------------------------------------------------------
extern "C" void kernel_launch(void* const* d_in, const int* in_sizes, int n_in,
                              void* d_out, int out_size) {
    const int*   frames = (const int*)d_in[0];
    const float* fc_w   = (const float*)d_in[1];
    const float* fc_b   = (const float*)d_in[2];
    float*       out    = (float*)d_out;

    hist_kernel<<<(BATCH * T) / FPB, 256>>>(frames);              // 1024 blocks
    band_kernel<<<dim3(T / TBLK, BATCH, KSPLIT), 256>>>();        // 512 blocks
    fc_kernel<<<(BATCH * T) / FROWS, 256>>>(fc_w, fc_b, out);     // 256 blocks
}